// round 16
// baseline (speedup 1.0000x reference)
#include <cuda_runtime.h>
#include <cuda_fp16.h>
#include <math.h>
#include <stdint.h>

#define BATCH 4
#define SEQ   1024
#define DM    512
#define NH    8
#define DH    64
#define DI    1024
#define DS    16
#define DTR   32
#define MTOK  (BATCH*SEQ)   // 4096

// ---------------- scratch (static device globals; no runtime allocation) ----
__device__ float g_q   [MTOK*DM];
__device__ float g_k   [MTOK*DM];
__device__ float g_v   [MTOK*DM];
__device__ float g_attn[MTOK*DM];
__device__ float g_tmp [MTOK*DM];
__device__ float g_x1  [MTOK*DM];
__device__ float g_x2  [MTOK*DM];
__device__ float g_xz  [MTOK*2*DI];
__device__ float g_u   [MTOK*DI];
__device__ float g_xdbl[MTOK*64];
__device__ float g_dt  [MTOK*DI];
__device__ float g_y   [MTOK*DI];
__device__ float g_ffn [MTOK*4*DM];

// ---------------- mma helpers ------------------------------------------------
__device__ __forceinline__ uint32_t f2tf32(float f) {
    uint32_t r;
    asm("cvt.rna.tf32.f32 %0, %1;" : "=r"(r) : "f"(f));
    return r;
}

__device__ __forceinline__ void mma_tf32(float c[4],
                                         uint32_t a0, uint32_t a1, uint32_t a2, uint32_t a3,
                                         uint32_t b0, uint32_t b1) {
    asm volatile(
        "mma.sync.aligned.m16n8k8.row.col.f32.tf32.tf32.f32 "
        "{%0,%1,%2,%3}, {%4,%5,%6,%7}, {%8,%9}, {%0,%1,%2,%3};"
        : "+f"(c[0]), "+f"(c[1]), "+f"(c[2]), "+f"(c[3])
        : "r"(a0), "r"(a1), "r"(a2), "r"(a3), "r"(b0), "r"(b1));
}

__device__ __forceinline__ void mma_f16(float c[4],
                                        uint32_t a0, uint32_t a1, uint32_t a2, uint32_t a3,
                                        uint32_t b0, uint32_t b1) {
    asm volatile(
        "mma.sync.aligned.m16n8k16.row.col.f32.f16.f16.f32 "
        "{%0,%1,%2,%3}, {%4,%5,%6,%7}, {%8,%9}, {%0,%1,%2,%3};"
        : "+f"(c[0]), "+f"(c[1]), "+f"(c[2]), "+f"(c[3])
        : "r"(a0), "r"(a1), "r"(a2), "r"(a3), "r"(b0), "r"(b1));
}

__device__ __forceinline__ uint32_t pack_h2(float lo, float hi) {
    __half2 h = __floats2half2_rn(lo, hi);
    return *(uint32_t*)&h;
}

#define GBM 128
#define GBN 64
#define HBK 64      // k elements per tile
#define APAD 36     // words per row (32 + 4 pad)
#define SMEM_GEMM ((2*GBM*APAD + 2*GBN*APAD) * 4)        // 55296 B (narrow/tf32)
#define SMEM_W    ((2*GBM*APAD + 2*128*APAD) * 4)        // 73728 B (wide)

// ---------------- WIDE fp16 GEMM: BM=128, BN=128 (deep grids only) ----------
template<int EPI>
__global__ __launch_bounds__(256) void gemm_w_kernel(
    const float* __restrict__ A, int lda,
    const float* __restrict__ W,
    const float* __restrict__ bias,
    float* __restrict__ C,
    int N, int K)
{
    extern __shared__ uint32_t sm[];
    uint32_t* As = sm;                       // [2][128*APAD]
    uint32_t* Bs = sm + 2*GBM*APAD;          // [2][128*APAD]

    const int tid  = threadIdx.x;
    const int wid  = tid >> 5;
    const int lane = tid & 31;
    const int warpM = wid & 1;
    const int warpN = wid >> 1;
    const int m0 = blockIdx.y * 128;
    const int n0 = blockIdx.x * 128;

    const int lr = lane >> 2;
    const int lc = lane & 3;

    const int lrow = tid >> 4;            // 0..15
    const int lcol = (tid & 15) * 4;      // float col
    const int lwrd = lcol >> 1;           // word col

    float acc[4][4][4];
#pragma unroll
    for (int i = 0; i < 4; i++)
#pragma unroll
        for (int j = 0; j < 4; j++)
#pragma unroll
            for (int e = 0; e < 4; e++) acc[i][j][e] = 0.f;

    float4 ra[8], rb[8];

#pragma unroll
    for (int i = 0; i < 8; i++)
        ra[i] = *(const float4*)&A[(size_t)(m0 + lrow + 16*i)*lda + lcol];
#pragma unroll
    for (int i = 0; i < 8; i++)
        rb[i] = *(const float4*)&W[(size_t)(n0 + lrow + 16*i)*K + lcol];
#pragma unroll
    for (int i = 0; i < 8; i++) {
        uint32_t* d = &As[(lrow + 16*i)*APAD + lwrd];
        d[0] = pack_h2(ra[i].x, ra[i].y);
        d[1] = pack_h2(ra[i].z, ra[i].w);
    }
#pragma unroll
    for (int i = 0; i < 8; i++) {
        uint32_t* d = &Bs[(lrow + 16*i)*APAD + lwrd];
        d[0] = pack_h2(rb[i].x, rb[i].y);
        d[1] = pack_h2(rb[i].z, rb[i].w);
    }
    __syncthreads();

    const int T = K / HBK;
    int buf = 0;
    for (int t = 0; t < T; t++) {
        if (t + 1 < T) {
            const int k0 = (t + 1) * HBK;
#pragma unroll
            for (int i = 0; i < 8; i++)
                ra[i] = *(const float4*)&A[(size_t)(m0 + lrow + 16*i)*lda + k0 + lcol];
#pragma unroll
            for (int i = 0; i < 8; i++)
                rb[i] = *(const float4*)&W[(size_t)(n0 + lrow + 16*i)*K + k0 + lcol];
        }

        const uint32_t* Ab = As + buf*GBM*APAD;
        const uint32_t* Bb = Bs + buf*128*APAD;
#pragma unroll
        for (int ks = 0; ks < 4; ks++) {
            const int kb = ks * 8;
            uint32_t af[4][4];
#pragma unroll
            for (int mt = 0; mt < 4; mt++) {
                const int rbse = warpM*64 + mt*16;
                af[mt][0] = Ab[(rbse + lr    )*APAD + kb + lc    ];
                af[mt][1] = Ab[(rbse + lr + 8)*APAD + kb + lc    ];
                af[mt][2] = Ab[(rbse + lr    )*APAD + kb + lc + 4];
                af[mt][3] = Ab[(rbse + lr + 8)*APAD + kb + lc + 4];
            }
            uint32_t bf[4][2];
#pragma unroll
            for (int nt = 0; nt < 4; nt++) {
                const int nb = warpN*32 + nt*8;
                bf[nt][0] = Bb[(nb + lr)*APAD + kb + lc    ];
                bf[nt][1] = Bb[(nb + lr)*APAD + kb + lc + 4];
            }
#pragma unroll
            for (int mt = 0; mt < 4; mt++)
#pragma unroll
                for (int nt = 0; nt < 4; nt++)
                    mma_f16(acc[mt][nt], af[mt][0], af[mt][1], af[mt][2], af[mt][3],
                            bf[nt][0], bf[nt][1]);
        }

        if (t + 1 < T) {
            uint32_t* An = As + (buf^1)*GBM*APAD;
            uint32_t* Bn = Bs + (buf^1)*128*APAD;
#pragma unroll
            for (int i = 0; i < 8; i++) {
                uint32_t* d = &An[(lrow + 16*i)*APAD + lwrd];
                d[0] = pack_h2(ra[i].x, ra[i].y);
                d[1] = pack_h2(ra[i].z, ra[i].w);
            }
#pragma unroll
            for (int i = 0; i < 8; i++) {
                uint32_t* d = &Bn[(lrow + 16*i)*APAD + lwrd];
                d[0] = pack_h2(rb[i].x, rb[i].y);
                d[1] = pack_h2(rb[i].z, rb[i].w);
            }
        }
        __syncthreads();
        buf ^= 1;
    }

#pragma unroll
    for (int mt = 0; mt < 4; mt++) {
#pragma unroll
        for (int nt = 0; nt < 4; nt++) {
#pragma unroll
            for (int e = 0; e < 4; e++) {
                const int row = m0 + warpM*64 + mt*16 + lr + (e >= 2 ? 8 : 0);
                const int col = n0 + warpN*32 + nt*8 + lc*2 + (e & 1);
                float vv = acc[mt][nt][e];
                if (EPI >= 1) vv += bias[col];
                if (EPI == 2) vv = 0.5f * vv * (1.f + erff(vv * 0.70710678118654752f));
                C[(size_t)row*N + col] = vv;
            }
        }
    }
}

// ---------------- narrow fp16 GEMM (verified R12) ---------------------------
template<int EPI>
__global__ __launch_bounds__(256) void gemm_h_kernel(
    const float* __restrict__ A, int lda,
    const float* __restrict__ W,
    const float* __restrict__ bias,
    float* __restrict__ C,
    int N, int K)
{
    extern __shared__ uint32_t sm[];
    uint32_t* As = sm;
    uint32_t* Bs = sm + 2*GBM*APAD;

    const int tid  = threadIdx.x;
    const int wid  = tid >> 5;
    const int lane = tid & 31;
    const int warpM = wid & 3;
    const int warpN = wid >> 2;
    const int m0 = blockIdx.y * GBM;
    const int n0 = blockIdx.x * GBN;

    const int lr = lane >> 2;
    const int lc = lane & 3;

    const int lrow = tid >> 4;
    const int lcol = (tid & 15) * 4;
    const int lwrd = lcol >> 1;

    float acc[2][4][4];
#pragma unroll
    for (int i = 0; i < 2; i++)
#pragma unroll
        for (int j = 0; j < 4; j++)
#pragma unroll
            for (int e = 0; e < 4; e++) acc[i][j][e] = 0.f;

    float4 ra[8], rb[4];

#pragma unroll
    for (int i = 0; i < 8; i++)
        ra[i] = *(const float4*)&A[(size_t)(m0 + lrow + 16*i)*lda + lcol];
#pragma unroll
    for (int i = 0; i < 4; i++)
        rb[i] = *(const float4*)&W[(size_t)(n0 + lrow + 16*i)*K + lcol];
#pragma unroll
    for (int i = 0; i < 8; i++) {
        uint32_t* d = &As[(lrow + 16*i)*APAD + lwrd];
        d[0] = pack_h2(ra[i].x, ra[i].y);
        d[1] = pack_h2(ra[i].z, ra[i].w);
    }
#pragma unroll
    for (int i = 0; i < 4; i++) {
        uint32_t* d = &Bs[(lrow + 16*i)*APAD + lwrd];
        d[0] = pack_h2(rb[i].x, rb[i].y);
        d[1] = pack_h2(rb[i].z, rb[i].w);
    }
    __syncthreads();

    const int T = K / HBK;
    int buf = 0;
    for (int t = 0; t < T; t++) {
        if (t + 1 < T) {
            const int k0 = (t + 1) * HBK;
#pragma unroll
            for (int i = 0; i < 8; i++)
                ra[i] = *(const float4*)&A[(size_t)(m0 + lrow + 16*i)*lda + k0 + lcol];
#pragma unroll
            for (int i = 0; i < 4; i++)
                rb[i] = *(const float4*)&W[(size_t)(n0 + lrow + 16*i)*K + k0 + lcol];
        }

        const uint32_t* Ab = As + buf*GBM*APAD;
        const uint32_t* Bb = Bs + buf*GBN*APAD;
#pragma unroll
        for (int ks = 0; ks < 4; ks++) {
            const int kb = ks * 8;
            uint32_t af[2][4];
#pragma unroll
            for (int mt = 0; mt < 2; mt++) {
                const int rbse = warpM*32 + mt*16;
                af[mt][0] = Ab[(rbse + lr    )*APAD + kb + lc    ];
                af[mt][1] = Ab[(rbse + lr + 8)*APAD + kb + lc    ];
                af[mt][2] = Ab[(rbse + lr    )*APAD + kb + lc + 4];
                af[mt][3] = Ab[(rbse + lr + 8)*APAD + kb + lc + 4];
            }
            uint32_t bf[4][2];
#pragma unroll
            for (int nt = 0; nt < 4; nt++) {
                const int nb = warpN*32 + nt*8;
                bf[nt][0] = Bb[(nb + lr)*APAD + kb + lc    ];
                bf[nt][1] = Bb[(nb + lr)*APAD + kb + lc + 4];
            }
#pragma unroll
            for (int mt = 0; mt < 2; mt++)
#pragma unroll
                for (int nt = 0; nt < 4; nt++)
                    mma_f16(acc[mt][nt], af[mt][0], af[mt][1], af[mt][2], af[mt][3],
                            bf[nt][0], bf[nt][1]);
        }

        if (t + 1 < T) {
            uint32_t* An = As + (buf^1)*GBM*APAD;
            uint32_t* Bn = Bs + (buf^1)*GBN*APAD;
#pragma unroll
            for (int i = 0; i < 8; i++) {
                uint32_t* d = &An[(lrow + 16*i)*APAD + lwrd];
                d[0] = pack_h2(ra[i].x, ra[i].y);
                d[1] = pack_h2(ra[i].z, ra[i].w);
            }
#pragma unroll
            for (int i = 0; i < 4; i++) {
                uint32_t* d = &Bn[(lrow + 16*i)*APAD + lwrd];
                d[0] = pack_h2(rb[i].x, rb[i].y);
                d[1] = pack_h2(rb[i].z, rb[i].w);
            }
        }
        __syncthreads();
        buf ^= 1;
    }

#pragma unroll
    for (int mt = 0; mt < 2; mt++) {
#pragma unroll
        for (int nt = 0; nt < 4; nt++) {
#pragma unroll
            for (int e = 0; e < 4; e++) {
                const int row = m0 + warpM*32 + mt*16 + lr + (e >= 2 ? 8 : 0);
                const int col = n0 + warpN*32 + nt*8 + lc*2 + (e & 1);
                float vv = acc[mt][nt][e];
                if (EPI >= 1) vv += bias[col];
                if (EPI == 2) vv = 0.5f * vv * (1.f + erff(vv * 0.70710678118654752f));
                C[(size_t)row*N + col] = vv;
            }
        }
    }
}

// ---------------- batched 2-output narrow GEMM (k & v in one launch) --------
// Identical body to gemm_h; blockIdx.z selects (Wa,biasa,Ca) or (Wb,biasb,Cb).
__global__ __launch_bounds__(256) void gemm_hz_kernel(
    const float* __restrict__ A, int lda,
    const float* __restrict__ Wa, const float* __restrict__ Wb,
    const float* __restrict__ biasa, const float* __restrict__ biasb,
    float* __restrict__ Ca, float* __restrict__ Cb,
    int N, int K)
{
    const float* W    = blockIdx.z ? Wb    : Wa;
    const float* bias = blockIdx.z ? biasb : biasa;
    float*       C    = blockIdx.z ? Cb    : Ca;

    extern __shared__ uint32_t sm[];
    uint32_t* As = sm;
    uint32_t* Bs = sm + 2*GBM*APAD;

    const int tid  = threadIdx.x;
    const int wid  = tid >> 5;
    const int lane = tid & 31;
    const int warpM = wid & 3;
    const int warpN = wid >> 2;
    const int m0 = blockIdx.y * GBM;
    const int n0 = blockIdx.x * GBN;

    const int lr = lane >> 2;
    const int lc = lane & 3;

    const int lrow = tid >> 4;
    const int lcol = (tid & 15) * 4;
    const int lwrd = lcol >> 1;

    float acc[2][4][4];
#pragma unroll
    for (int i = 0; i < 2; i++)
#pragma unroll
        for (int j = 0; j < 4; j++)
#pragma unroll
            for (int e = 0; e < 4; e++) acc[i][j][e] = 0.f;

    float4 ra[8], rb[4];

#pragma unroll
    for (int i = 0; i < 8; i++)
        ra[i] = *(const float4*)&A[(size_t)(m0 + lrow + 16*i)*lda + lcol];
#pragma unroll
    for (int i = 0; i < 4; i++)
        rb[i] = *(const float4*)&W[(size_t)(n0 + lrow + 16*i)*K + lcol];
#pragma unroll
    for (int i = 0; i < 8; i++) {
        uint32_t* d = &As[(lrow + 16*i)*APAD + lwrd];
        d[0] = pack_h2(ra[i].x, ra[i].y);
        d[1] = pack_h2(ra[i].z, ra[i].w);
    }
#pragma unroll
    for (int i = 0; i < 4; i++) {
        uint32_t* d = &Bs[(lrow + 16*i)*APAD + lwrd];
        d[0] = pack_h2(rb[i].x, rb[i].y);
        d[1] = pack_h2(rb[i].z, rb[i].w);
    }
    __syncthreads();

    const int T = K / HBK;
    int buf = 0;
    for (int t = 0; t < T; t++) {
        if (t + 1 < T) {
            const int k0 = (t + 1) * HBK;
#pragma unroll
            for (int i = 0; i < 8; i++)
                ra[i] = *(const float4*)&A[(size_t)(m0 + lrow + 16*i)*lda + k0 + lcol];
#pragma unroll
            for (int i = 0; i < 4; i++)
                rb[i] = *(const float4*)&W[(size_t)(n0 + lrow + 16*i)*K + k0 + lcol];
        }

        const uint32_t* Ab = As + buf*GBM*APAD;
        const uint32_t* Bb = Bs + buf*GBN*APAD;
#pragma unroll
        for (int ks = 0; ks < 4; ks++) {
            const int kb = ks * 8;
            uint32_t af[2][4];
#pragma unroll
            for (int mt = 0; mt < 2; mt++) {
                const int rbse = warpM*32 + mt*16;
                af[mt][0] = Ab[(rbse + lr    )*APAD + kb + lc    ];
                af[mt][1] = Ab[(rbse + lr + 8)*APAD + kb + lc    ];
                af[mt][2] = Ab[(rbse + lr    )*APAD + kb + lc + 4];
                af[mt][3] = Ab[(rbse + lr + 8)*APAD + kb + lc + 4];
            }
            uint32_t bf[4][2];
#pragma unroll
            for (int nt = 0; nt < 4; nt++) {
                const int nb = warpN*32 + nt*8;
                bf[nt][0] = Bb[(nb + lr)*APAD + kb + lc    ];
                bf[nt][1] = Bb[(nb + lr)*APAD + kb + lc + 4];
            }
#pragma unroll
            for (int mt = 0; mt < 2; mt++)
#pragma unroll
                for (int nt = 0; nt < 4; nt++)
                    mma_f16(acc[mt][nt], af[mt][0], af[mt][1], af[mt][2], af[mt][3],
                            bf[nt][0], bf[nt][1]);
        }

        if (t + 1 < T) {
            uint32_t* An = As + (buf^1)*GBM*APAD;
            uint32_t* Bn = Bs + (buf^1)*GBN*APAD;
#pragma unroll
            for (int i = 0; i < 8; i++) {
                uint32_t* d = &An[(lrow + 16*i)*APAD + lwrd];
                d[0] = pack_h2(ra[i].x, ra[i].y);
                d[1] = pack_h2(ra[i].z, ra[i].w);
            }
#pragma unroll
            for (int i = 0; i < 4; i++) {
                uint32_t* d = &Bn[(lrow + 16*i)*APAD + lwrd];
                d[0] = pack_h2(rb[i].x, rb[i].y);
                d[1] = pack_h2(rb[i].z, rb[i].w);
            }
        }
        __syncthreads();
        buf ^= 1;
    }

#pragma unroll
    for (int mt = 0; mt < 2; mt++) {
#pragma unroll
        for (int nt = 0; nt < 4; nt++) {
#pragma unroll
            for (int e = 0; e < 4; e++) {
                const int row = m0 + warpM*32 + mt*16 + lr + (e >= 2 ? 8 : 0);
                const int col = n0 + warpN*32 + nt*8 + lc*2 + (e & 1);
                float vv = acc[mt][nt][e] + bias[col];
                C[(size_t)row*N + col] = vv;
            }
        }
    }
}

// ---------------- tf32 GEMM (kept for K=32 dt-projection, EPI=3 softplus) ---
#define GBK 32
template<int EPI>
__global__ __launch_bounds__(256) void gemm_tc_kernel(
    const float* __restrict__ A, int lda,
    const float* __restrict__ W,
    const float* __restrict__ bias,
    float* __restrict__ C,
    int N, int K)
{
    extern __shared__ uint32_t sm[];
    uint32_t* As = sm;
    uint32_t* Bs = sm + 2*GBM*APAD;

    const int tid  = threadIdx.x;
    const int wid  = tid >> 5;
    const int lane = tid & 31;
    const int warpM = wid & 3;
    const int warpN = wid >> 2;
    const int m0 = blockIdx.y * GBM;
    const int n0 = blockIdx.x * GBN;
    const int lr = lane >> 2;
    const int lc = lane & 3;
    const int lrow = tid >> 3;
    const int lcol = (tid & 7) * 4;

    float acc[2][4][4];
#pragma unroll
    for (int i = 0; i < 2; i++)
#pragma unroll
        for (int j = 0; j < 4; j++)
#pragma unroll
            for (int e = 0; e < 4; e++) acc[i][j][e] = 0.f;

    float4 ra[4], rb[2];
    {
#pragma unroll
        for (int i = 0; i < 4; i++)
            ra[i] = *(const float4*)&A[(size_t)(m0 + lrow + 32*i)*lda + lcol];
#pragma unroll
        for (int i = 0; i < 2; i++)
            rb[i] = *(const float4*)&W[(size_t)(n0 + lrow + 32*i)*K + lcol];
#pragma unroll
        for (int i = 0; i < 4; i++) {
            uint32_t* d = &As[(lrow + 32*i)*APAD + lcol];
            d[0] = f2tf32(ra[i].x); d[1] = f2tf32(ra[i].y);
            d[2] = f2tf32(ra[i].z); d[3] = f2tf32(ra[i].w);
        }
#pragma unroll
        for (int i = 0; i < 2; i++) {
            uint32_t* d = &Bs[(lrow + 32*i)*APAD + lcol];
            d[0] = f2tf32(rb[i].x); d[1] = f2tf32(rb[i].y);
            d[2] = f2tf32(rb[i].z); d[3] = f2tf32(rb[i].w);
        }
    }
    __syncthreads();

    const int T = K / GBK;
    int buf = 0;
    for (int t = 0; t < T; t++) {
        if (t + 1 < T) {
            const int k0 = (t + 1) * GBK;
#pragma unroll
            for (int i = 0; i < 4; i++)
                ra[i] = *(const float4*)&A[(size_t)(m0 + lrow + 32*i)*lda + k0 + lcol];
#pragma unroll
            for (int i = 0; i < 2; i++)
                rb[i] = *(const float4*)&W[(size_t)(n0 + lrow + 32*i)*K + k0 + lcol];
        }
        const uint32_t* Ab = As + buf*GBM*APAD;
        const uint32_t* Bb = Bs + buf*GBN*APAD;
#pragma unroll
        for (int ks = 0; ks < 4; ks++) {
            const int kb = ks * 8;
            uint32_t af[2][4];
#pragma unroll
            for (int mt = 0; mt < 2; mt++) {
                const int rbse = warpM*32 + mt*16;
                af[mt][0] = Ab[(rbse + lr    )*APAD + kb + lc    ];
                af[mt][1] = Ab[(rbse + lr + 8)*APAD + kb + lc    ];
                af[mt][2] = Ab[(rbse + lr    )*APAD + kb + lc + 4];
                af[mt][3] = Ab[(rbse + lr + 8)*APAD + kb + lc + 4];
            }
            uint32_t bf[4][2];
#pragma unroll
            for (int nt = 0; nt < 4; nt++) {
                const int nb = warpN*32 + nt*8;
                bf[nt][0] = Bb[(nb + lr)*APAD + kb + lc    ];
                bf[nt][1] = Bb[(nb + lr)*APAD + kb + lc + 4];
            }
#pragma unroll
            for (int mt = 0; mt < 2; mt++)
#pragma unroll
                for (int nt = 0; nt < 4; nt++)
                    mma_tf32(acc[mt][nt], af[mt][0], af[mt][1], af[mt][2], af[mt][3],
                             bf[nt][0], bf[nt][1]);
        }
        if (t + 1 < T) {
            uint32_t* An = As + (buf^1)*GBM*APAD;
            uint32_t* Bn = Bs + (buf^1)*GBN*APAD;
#pragma unroll
            for (int i = 0; i < 4; i++) {
                uint32_t* d = &An[(lrow + 32*i)*APAD + lcol];
                d[0] = f2tf32(ra[i].x); d[1] = f2tf32(ra[i].y);
                d[2] = f2tf32(ra[i].z); d[3] = f2tf32(ra[i].w);
            }
#pragma unroll
            for (int i = 0; i < 2; i++) {
                uint32_t* d = &Bn[(lrow + 32*i)*APAD + lcol];
                d[0] = f2tf32(rb[i].x); d[1] = f2tf32(rb[i].y);
                d[2] = f2tf32(rb[i].z); d[3] = f2tf32(rb[i].w);
            }
        }
        __syncthreads();
        buf ^= 1;
    }

#pragma unroll
    for (int mt = 0; mt < 2; mt++) {
#pragma unroll
        for (int nt = 0; nt < 4; nt++) {
#pragma unroll
            for (int e = 0; e < 4; e++) {
                const int row = m0 + warpM*32 + mt*16 + lr + (e >= 2 ? 8 : 0);
                const int col = n0 + warpN*32 + nt*8 + lc*2 + (e & 1);
                float vv = acc[mt][nt][e];
                if (EPI >= 1) vv += bias[col];
                if (EPI == 3) vv = (vv > 20.f) ? vv : log1pf(expf(vv));
                C[(size_t)row*N + col] = vv;
            }
        }
    }
}

// ---------------- fp16 flash attention: 128 q-rows / 8 warps per block ------
#define KWST 36
#define VTST 17
#define PST  20

__global__ __launch_bounds__(256) void attn_h_kernel(
    const float* __restrict__ q, const float* __restrict__ k,
    const float* __restrict__ v, float* __restrict__ out)
{
    __shared__ uint32_t Ks[32*KWST];          // [key][ch-word 0..31]
    __shared__ uint32_t Vt[64*VTST];          // [ch][key-word 0..15]
    __shared__ uint32_t Ps[8][16*PST];        // per-warp [row][key-word]

    const int b = blockIdx.z, h = blockIdx.y;
    const int q0 = blockIdx.x * 128;
    const int tid = threadIdx.x;
    const int wid = tid >> 5;      // 0..7
    const int lane = tid & 31;
    const int lr = lane >> 2;
    const int lc = lane & 3;

    uint32_t Qf[4][4];
    {
        const float* q_r0 = q + (size_t)(b*SEQ + q0 + wid*16 + lr    )*DM + h*DH;
        const float* q_r1 = q + (size_t)(b*SEQ + q0 + wid*16 + lr + 8)*DM + h*DH;
#pragma unroll
        for (int ks = 0; ks < 4; ks++) {
            const int c0 = ks*16 + 2*lc;
            Qf[ks][0] = pack_h2(q_r0[c0    ]*0.125f, q_r0[c0 + 1]*0.125f);
            Qf[ks][1] = pack_h2(q_r1[c0    ]*0.125f, q_r1[c0 + 1]*0.125f);
            Qf[ks][2] = pack_h2(q_r0[c0 + 8]*0.125f, q_r0[c0 + 9]*0.125f);
            Qf[ks][3] = pack_h2(q_r1[c0 + 8]*0.125f, q_r1[c0 + 9]*0.125f);
        }
    }

    float Oacc[8][4];
#pragma unroll
    for (int nb = 0; nb < 8; nb++)
#pragma unroll
        for (int e = 0; e < 4; e++) Oacc[nb][e] = 0.f;
    float m0 = -1e30f, m1 = -1e30f, l0 = 0.f, l1 = 0.f;

    for (int t0 = 0; t0 < SEQ; t0 += 32) {
        __syncthreads();
        // K tile: 256 threads, 8 threads/key, 8 ch each -> 4 half2 words
        {
            const int j = tid >> 3;              // key 0..31
            const int c0 = (tid & 7) * 8;        // channel base
            const float4 k0v = *(const float4*)&k[(size_t)(b*SEQ + t0 + j)*DM + h*DH + c0];
            const float4 k1v = *(const float4*)&k[(size_t)(b*SEQ + t0 + j)*DM + h*DH + c0 + 4];
            uint32_t* dst = &Ks[j*KWST + (c0 >> 1)];
            dst[0] = pack_h2(k0v.x, k0v.y);
            dst[1] = pack_h2(k0v.z, k0v.w);
            dst[2] = pack_h2(k1v.x, k1v.y);
            dst[3] = pack_h2(k1v.z, k1v.w);
        }
        // V tile transposed: thread owns key-pair jp, 4 channels
        {
            const int jp = tid >> 4;             // key-pair 0..15
            const int c4 = (tid & 15) * 4;       // channel base
            const float4 a0 = *(const float4*)&v[(size_t)(b*SEQ + t0 + 2*jp    )*DM + h*DH + c4];
            const float4 b0 = *(const float4*)&v[(size_t)(b*SEQ + t0 + 2*jp + 1)*DM + h*DH + c4];
            Vt[(c4+0)*VTST + jp] = pack_h2(a0.x, b0.x);
            Vt[(c4+1)*VTST + jp] = pack_h2(a0.y, b0.y);
            Vt[(c4+2)*VTST + jp] = pack_h2(a0.z, b0.z);
            Vt[(c4+3)*VTST + jp] = pack_h2(a0.w, b0.w);
        }
        __syncthreads();

        // S = Q @ K^T
        float Sacc[4][4];
#pragma unroll
        for (int nb = 0; nb < 4; nb++)
#pragma unroll
            for (int e = 0; e < 4; e++) Sacc[nb][e] = 0.f;
#pragma unroll
        for (int ks = 0; ks < 4; ks++) {
            const int kb = ks * 8;
            uint32_t bf[4][2];
#pragma unroll
            for (int nb = 0; nb < 4; nb++) {
                bf[nb][0] = Ks[(nb*8 + lr)*KWST + kb + lc    ];
                bf[nb][1] = Ks[(nb*8 + lr)*KWST + kb + lc + 4];
            }
#pragma unroll
            for (int nb = 0; nb < 4; nb++)
                mma_f16(Sacc[nb], Qf[ks][0], Qf[ks][1], Qf[ks][2], Qf[ks][3],
                        bf[nb][0], bf[nb][1]);
        }

        // online softmax
        float tmax0 = -1e30f, tmax1 = -1e30f;
#pragma unroll
        for (int nb = 0; nb < 4; nb++) {
            tmax0 = fmaxf(tmax0, fmaxf(Sacc[nb][0], Sacc[nb][1]));
            tmax1 = fmaxf(tmax1, fmaxf(Sacc[nb][2], Sacc[nb][3]));
        }
        tmax0 = fmaxf(tmax0, __shfl_xor_sync(0xffffffffu, tmax0, 1));
        tmax0 = fmaxf(tmax0, __shfl_xor_sync(0xffffffffu, tmax0, 2));
        tmax1 = fmaxf(tmax1, __shfl_xor_sync(0xffffffffu, tmax1, 1));
        tmax1 = fmaxf(tmax1, __shfl_xor_sync(0xffffffffu, tmax1, 2));

        const float m0n = fmaxf(m0, tmax0), m1n = fmaxf(m1, tmax1);
        const float c0 = __expf(m0 - m0n), c1 = __expf(m1 - m1n);
        m0 = m0n; m1 = m1n;

        float s0 = 0.f, s1 = 0.f;
        uint32_t* Pw = Ps[wid];
#pragma unroll
        for (int nb = 0; nb < 4; nb++) {
            const float p00 = __expf(Sacc[nb][0] - m0);
            const float p01 = __expf(Sacc[nb][1] - m0);
            const float p10 = __expf(Sacc[nb][2] - m1);
            const float p11 = __expf(Sacc[nb][3] - m1);
            s0 += p00 + p01; s1 += p10 + p11;
            Pw[(lr    )*PST + nb*4 + lc] = pack_h2(p00, p01);
            Pw[(lr + 8)*PST + nb*4 + lc] = pack_h2(p10, p11);
        }
        s0 += __shfl_xor_sync(0xffffffffu, s0, 1);
        s0 += __shfl_xor_sync(0xffffffffu, s0, 2);
        s1 += __shfl_xor_sync(0xffffffffu, s1, 1);
        s1 += __shfl_xor_sync(0xffffffffu, s1, 2);
        l0 = l0*c0 + s0;
        l1 = l1*c1 + s1;

#pragma unroll
        for (int nb = 0; nb < 8; nb++) {
            Oacc[nb][0] *= c0; Oacc[nb][1] *= c0;
            Oacc[nb][2] *= c1; Oacc[nb][3] *= c1;
        }
        __syncwarp();

        // O += P @ V
#pragma unroll
        for (int ks = 0; ks < 2; ks++) {
            const int kb = ks * 8;
            uint32_t Pf[4];
            Pf[0] = Pw[(lr    )*PST + kb + lc    ];
            Pf[1] = Pw[(lr + 8)*PST + kb + lc    ];
            Pf[2] = Pw[(lr    )*PST + kb + lc + 4];
            Pf[3] = Pw[(lr + 8)*PST + kb + lc + 4];
#pragma unroll
            for (int nb = 0; nb < 8; nb++) {
                uint32_t vf0 = Vt[(nb*8 + lr)*VTST + kb + lc    ];
                uint32_t vf1 = Vt[(nb*8 + lr)*VTST + kb + lc + 4];
                mma_f16(Oacc[nb], Pf[0], Pf[1], Pf[2], Pf[3], vf0, vf1);
            }
        }
    }

    const float inv0 = 1.f / l0, inv1 = 1.f / l1;
    float* o_r0 = out + (size_t)(b*SEQ + q0 + wid*16 + lr    )*DM + h*DH;
    float* o_r1 = out + (size_t)(b*SEQ + q0 + wid*16 + lr + 8)*DM + h*DH;
#pragma unroll
    for (int nb = 0; nb < 8; nb++) {
        o_r0[nb*8 + lc*2    ] = Oacc[nb][0] * inv0;
        o_r0[nb*8 + lc*2 + 1] = Oacc[nb][1] * inv0;
        o_r1[nb*8 + lc*2    ] = Oacc[nb][2] * inv1;
        o_r1[nb*8 + lc*2 + 1] = Oacc[nb][3] * inv1;
    }
}

// ---------------- layernorm(a + r): one warp per row ------------------------
__global__ __launch_bounds__(128) void ln_kernel(
    const float* __restrict__ a, const float* __restrict__ r,
    const float* __restrict__ g, const float* __restrict__ bt,
    float* __restrict__ out)
{
    const int row  = blockIdx.x*4 + (threadIdx.x >> 5);
    const int lane = threadIdx.x & 31;
    const size_t base = (size_t)row * DM;

    float vv[16];
    float sum = 0.f;
#pragma unroll
    for (int i = 0; i < 16; i++) {
        const int e = lane + i*32;
        vv[i] = a[base+e] + r[base+e];
        sum += vv[i];
    }
#pragma unroll
    for (int o = 16; o > 0; o >>= 1) sum += __shfl_xor_sync(0xffffffffu, sum, o);
    const float mu = sum * (1.f/DM);

    float sq = 0.f;
#pragma unroll
    for (int i = 0; i < 16; i++) { const float d = vv[i] - mu; sq = fmaf(d, d, sq); }
#pragma unroll
    for (int o = 16; o > 0; o >>= 1) sq += __shfl_xor_sync(0xffffffffu, sq, o);
    const float rstd = rsqrtf(sq * (1.f/DM) + 1e-5f);

#pragma unroll
    for (int i = 0; i < 16; i++) {
        const int e = lane + i*32;
        out[base+e] = (vv[i]-mu)*rstd*g[e] + bt[e];
    }
}

// ---------------- depthwise causal conv (D_CONV=4) + SiLU -------------------
__global__ void conv_silu_kernel(
    const float* __restrict__ xz, const float* __restrict__ cw,
    const float* __restrict__ cb, float* __restrict__ u)
{
    const int idx = blockIdx.x*256 + threadIdx.x;
    const int d = idx & (DI-1);
    const int t = (idx >> 10) & (SEQ-1);
    const int b = idx >> 20;
    float s = cb[d];
#pragma unroll
    for (int j = 0; j < 4; j++) {
        const int tt = t - 3 + j;
        if (tt >= 0)
            s = fmaf(xz[((size_t)(b*SEQ + tt) << 11) + d], cw[d*4 + j], s);
    }
    const float sg = 1.f / (1.f + __expf(-s));
    u[idx] = s * sg;
}

// ---------------- selective scan: thread-pair per channel (s split 8+8) -----
__global__ __launch_bounds__(64) void scan_kernel(
    const float* __restrict__ dt, const float* __restrict__ u,
    const float* __restrict__ xz, const float* __restrict__ xdbl,
    const float* __restrict__ A_log, const float* __restrict__ D_p,
    float* __restrict__ yout)
{
    const int b = blockIdx.x >> 5;
    const int dbase = (blockIdx.x & 31) << 5;
    const int ch = threadIdx.x >> 1;          // 0..31
    const int sh = (threadIdx.x & 1) * 8;     // state offset 0 or 8
    const int d = dbase + ch;

    float A[8];
#pragma unroll
    for (int s = 0; s < 8; s++) A[s] = -expf(A_log[d*DS + sh + s]);
    float h[8];
#pragma unroll
    for (int s = 0; s < 8; s++) h[s] = 0.f;
    const float Dp = D_p[d];

    __shared__ float Bs[64][DS];
    __shared__ float Cs[64][DS];
    __shared__ float dts[64][32];
    __shared__ float us [64][32];
    __shared__ float zs [64][32];

    for (int t0 = 0; t0 < SEQ; t0 += 64) {
        __syncthreads();
        for (int i = threadIdx.x; i < 64*DS; i += 64) {
            const int tt = i >> 4, s = i & 15;
            const size_t rb = (size_t)(b*SEQ + t0 + tt) * 64;
            Bs[tt][s] = xdbl[rb + DTR + s];
            Cs[tt][s] = xdbl[rb + DTR + DS + s];
        }
        for (int i = threadIdx.x; i < 64*8; i += 64) {
            const int tt = i >> 3, c4 = (i & 7) * 4;
            const size_t ro = (size_t)(b*SEQ + t0 + tt);
            *(float4*)&dts[tt][c4] = *(const float4*)&dt[ro*DI + dbase + c4];
            *(float4*)&us [tt][c4] = *(const float4*)&u [ro*DI + dbase + c4];
            *(float4*)&zs [tt][c4] = *(const float4*)&xz[(ro << 11) + DI + dbase + c4];
        }
        __syncthreads();

        for (int tt = 0; tt < 64; tt++) {
            const float dtv = dts[tt][ch];
            const float uv  = us [tt][ch];
            const float du  = dtv * uv;
            float y = 0.f;
#pragma unroll
            for (int s = 0; s < 8; s++) {
                const float dA = __expf(dtv * A[s]);
                h[s] = fmaf(h[s], dA, du * Bs[tt][sh + s]);
                y = fmaf(h[s], Cs[tt][sh + s], y);
            }
            y += __shfl_xor_sync(0xffffffffu, y, 1);
            if ((threadIdx.x & 1) == 0) {
                const float zv = zs[tt][ch];
                const float sg = zv / (1.f + __expf(-zv));
                yout[(size_t)(b*SEQ + t0 + tt)*DI + d] = (y + uv*Dp) * sg;
            }
        }
    }
}

// ---------------- launcher --------------------------------------------------
extern "C" void kernel_launch(void* const* d_in, const int* /*in_sizes*/, int /*n_in*/,
                              void* d_out, int /*out_size*/)
{
    const float* x      = (const float*)d_in[0];
    const float* mem    = (const float*)d_in[1];
    const float* Wq     = (const float*)d_in[2];
    const float* bq     = (const float*)d_in[3];
    const float* Wk     = (const float*)d_in[4];
    const float* bk     = (const float*)d_in[5];
    const float* Wv     = (const float*)d_in[6];
    const float* bv     = (const float*)d_in[7];
    const float* Wo     = (const float*)d_in[8];
    const float* bo     = (const float*)d_in[9];
    const float* ln1g   = (const float*)d_in[10];
    const float* ln1b   = (const float*)d_in[11];
    const float* ln2g   = (const float*)d_in[12];
    const float* ln2b   = (const float*)d_in[13];
    const float* ln3g   = (const float*)d_in[14];
    const float* ln3b   = (const float*)d_in[15];
    const float* W_in   = (const float*)d_in[16];
    const float* conv_w = (const float*)d_in[17];
    const float* conv_b = (const float*)d_in[18];
    const float* W_xprj = (const float*)d_in[19];
    const float* W_dt   = (const float*)d_in[20];
    const float* b_dt   = (const float*)d_in[21];
    const float* A_log  = (const float*)d_in[22];
    const float* D_p    = (const float*)d_in[23];
    const float* W_out  = (const float*)d_in[24];
    const float* W1     = (const float*)d_in[25];
    const float* b1     = (const float*)d_in[26];
    const float* W2     = (const float*)d_in[27];
    const float* b2     = (const float*)d_in[28];

    float *q, *k, *v, *attn, *tmp, *x1, *x2, *xz, *u, *xdbl, *dtb, *y, *ffn;
    cudaGetSymbolAddress((void**)&q,    g_q);
    cudaGetSymbolAddress((void**)&k,    g_k);
    cudaGetSymbolAddress((void**)&v,    g_v);
    cudaGetSymbolAddress((void**)&attn, g_attn);
    cudaGetSymbolAddress((void**)&tmp,  g_tmp);
    cudaGetSymbolAddress((void**)&x1,   g_x1);
    cudaGetSymbolAddress((void**)&x2,   g_x2);
    cudaGetSymbolAddress((void**)&xz,   g_xz);
    cudaGetSymbolAddress((void**)&u,    g_u);
    cudaGetSymbolAddress((void**)&xdbl, g_xdbl);
    cudaGetSymbolAddress((void**)&dtb,  g_dt);
    cudaGetSymbolAddress((void**)&y,    g_y);
    cudaGetSymbolAddress((void**)&ffn,  g_ffn);

    // opt in to >48KB dynamic smem (idempotent, host-side, capture-safe)
    cudaFuncSetAttribute(gemm_w_kernel<0>, cudaFuncAttributeMaxDynamicSharedMemorySize, SMEM_W);
    cudaFuncSetAttribute(gemm_w_kernel<1>, cudaFuncAttributeMaxDynamicSharedMemorySize, SMEM_W);
    cudaFuncSetAttribute(gemm_w_kernel<2>, cudaFuncAttributeMaxDynamicSharedMemorySize, SMEM_W);
    cudaFuncSetAttribute(gemm_h_kernel<0>, cudaFuncAttributeMaxDynamicSharedMemorySize, SMEM_GEMM);
    cudaFuncSetAttribute(gemm_h_kernel<1>, cudaFuncAttributeMaxDynamicSharedMemorySize, SMEM_GEMM);
    cudaFuncSetAttribute(gemm_hz_kernel,   cudaFuncAttributeMaxDynamicSharedMemorySize, SMEM_GEMM);
    cudaFuncSetAttribute(gemm_tc_kernel<3>, cudaFuncAttributeMaxDynamicSharedMemorySize, SMEM_GEMM);

    const dim3 gRowN(DM/GBN,   MTOK/GBM);      // (8, 32)  narrow N=512
    const dim3 gKV (DM/GBN,    MTOK/GBM, 2);   // (8, 32, 2)
    const dim3 gBigW(2048/128, MTOK/128);      // (16, 32) wide N=2048
    const dim3 gXp (64/GBN,    MTOK/GBM);      // (1, 32)
    const dim3 gDt (DI/GBN,    MTOK/GBM);      // (16, 32)

    // --- cross attention ---
    gemm_h_kernel<1><<<gRowN, 256, SMEM_GEMM>>>(x, DM, Wq, bq, q, DM, DM);
    gemm_hz_kernel<<<gKV, 256, SMEM_GEMM>>>(mem, DM, Wk, Wv, bk, bv, k, v, DM, DM);
    attn_h_kernel<<<dim3(SEQ/128, NH, BATCH), 256>>>(q, k, v, attn);
    gemm_h_kernel<1><<<gRowN, 256, SMEM_GEMM>>>(attn, DM, Wo, bo, tmp, DM, DM);
    ln_kernel<<<MTOK/4, 128>>>(x, tmp, ln1g, ln1b, x1);

    // --- mamba ---
    gemm_w_kernel<0><<<gBigW, 256, SMEM_W>>>(x1, DM, W_in, nullptr, xz, 2*DI, DM);
    conv_silu_kernel<<<(MTOK*DI)/256, 256>>>(xz, conv_w, conv_b, u);
    gemm_h_kernel<0><<<gXp, 256, SMEM_GEMM>>>(u, DI, W_xprj, nullptr, xdbl, 64, DI);
    gemm_tc_kernel<3><<<gDt, 256, SMEM_GEMM>>>(xdbl, 64, W_dt, b_dt, dtb, DI, DTR);
    scan_kernel<<<128, 64>>>(dtb, u, xz, xdbl, A_log, D_p, y);
    gemm_h_kernel<0><<<gRowN, 256, SMEM_GEMM>>>(y, DI, W_out, nullptr, tmp, DM, DI);
    ln_kernel<<<MTOK/4, 128>>>(x1, tmp, ln2g, ln2b, x2);

    // --- ffn ---
    gemm_w_kernel<2><<<gBigW, 256, SMEM_W>>>(x2, DM, W1, b1, ffn, 2048, DM);
    gemm_h_kernel<1><<<gRowN, 256, SMEM_GEMM>>>(ffn, 2048, W2, b2, tmp, DM, 2048);
    ln_kernel<<<MTOK/4, 128>>>(x2, tmp, ln3g, ln3b, (float*)d_out);
}

// round 17
// speedup vs baseline: 1.0778x; 1.0778x over previous
#include <cuda_runtime.h>
#include <cuda_fp16.h>
#include <math.h>
#include <stdint.h>

#define BATCH 4
#define SEQ   1024
#define DM    512
#define NH    8
#define DH    64
#define DI    1024
#define DS    16
#define DTR   32
#define MTOK  (BATCH*SEQ)   // 4096

// ---------------- scratch (static device globals; no runtime allocation) ----
__device__ float g_q   [MTOK*DM];
__device__ float g_k   [MTOK*DM];
__device__ float g_v   [MTOK*DM];
__device__ float g_attn[MTOK*DM];
__device__ float g_tmp [MTOK*DM];
__device__ float g_x1  [MTOK*DM];
__device__ float g_x2  [MTOK*DM];
__device__ float g_xz  [MTOK*2*DI];
__device__ float g_u   [MTOK*DI];
__device__ float g_xdbl[MTOK*64];
__device__ float g_dt  [MTOK*DI];
__device__ float g_y   [MTOK*DI];
__device__ float g_ffn [MTOK*4*DM];

// ---------------- mma helpers ------------------------------------------------
__device__ __forceinline__ uint32_t f2tf32(float f) {
    uint32_t r;
    asm("cvt.rna.tf32.f32 %0, %1;" : "=r"(r) : "f"(f));
    return r;
}

__device__ __forceinline__ void mma_tf32(float c[4],
                                         uint32_t a0, uint32_t a1, uint32_t a2, uint32_t a3,
                                         uint32_t b0, uint32_t b1) {
    asm volatile(
        "mma.sync.aligned.m16n8k8.row.col.f32.tf32.tf32.f32 "
        "{%0,%1,%2,%3}, {%4,%5,%6,%7}, {%8,%9}, {%0,%1,%2,%3};"
        : "+f"(c[0]), "+f"(c[1]), "+f"(c[2]), "+f"(c[3])
        : "r"(a0), "r"(a1), "r"(a2), "r"(a3), "r"(b0), "r"(b1));
}

__device__ __forceinline__ void mma_f16(float c[4],
                                        uint32_t a0, uint32_t a1, uint32_t a2, uint32_t a3,
                                        uint32_t b0, uint32_t b1) {
    asm volatile(
        "mma.sync.aligned.m16n8k16.row.col.f32.f16.f16.f32 "
        "{%0,%1,%2,%3}, {%4,%5,%6,%7}, {%8,%9}, {%0,%1,%2,%3};"
        : "+f"(c[0]), "+f"(c[1]), "+f"(c[2]), "+f"(c[3])
        : "r"(a0), "r"(a1), "r"(a2), "r"(a3), "r"(b0), "r"(b1));
}

__device__ __forceinline__ uint32_t pack_h2(float lo, float hi) {
    __half2 h = __floats2half2_rn(lo, hi);
    return *(uint32_t*)&h;
}

#define GBM 128
#define GBN 64
#define HBK 64      // k elements per tile
#define APAD 36     // words per row (32 + 4 pad)
#define SMEM_GEMM ((2*GBM*APAD + 2*GBN*APAD) * 4)        // 55296 B (narrow/tf32)
#define SMEM_W    ((2*GBM*APAD + 2*128*APAD) * 4)        // 73728 B (wide)

// ---------------- wide fp16 GEMM body (BM=128, BN=128, 2Mx4N) ---------------
// Shared by the plain kernel and the z-batched qkv kernel.
template<int EPI>
__device__ __forceinline__ void gemm_w_body(
    const float* __restrict__ A, int lda,
    const float* __restrict__ W,
    const float* __restrict__ bias,
    float* __restrict__ C,
    int N, int K)
{
    extern __shared__ uint32_t sm[];
    uint32_t* As = sm;                       // [2][128*APAD]
    uint32_t* Bs = sm + 2*GBM*APAD;          // [2][128*APAD]

    const int tid  = threadIdx.x;
    const int wid  = tid >> 5;
    const int lane = tid & 31;
    const int warpM = wid & 1;
    const int warpN = wid >> 1;
    const int m0 = blockIdx.y * 128;
    const int n0 = blockIdx.x * 128;

    const int lr = lane >> 2;
    const int lc = lane & 3;

    const int lrow = tid >> 4;            // 0..15
    const int lcol = (tid & 15) * 4;      // float col
    const int lwrd = lcol >> 1;           // word col

    float acc[4][4][4];
#pragma unroll
    for (int i = 0; i < 4; i++)
#pragma unroll
        for (int j = 0; j < 4; j++)
#pragma unroll
            for (int e = 0; e < 4; e++) acc[i][j][e] = 0.f;

    float4 ra[8], rb[8];

#pragma unroll
    for (int i = 0; i < 8; i++)
        ra[i] = *(const float4*)&A[(size_t)(m0 + lrow + 16*i)*lda + lcol];
#pragma unroll
    for (int i = 0; i < 8; i++)
        rb[i] = *(const float4*)&W[(size_t)(n0 + lrow + 16*i)*K + lcol];
#pragma unroll
    for (int i = 0; i < 8; i++) {
        uint32_t* d = &As[(lrow + 16*i)*APAD + lwrd];
        d[0] = pack_h2(ra[i].x, ra[i].y);
        d[1] = pack_h2(ra[i].z, ra[i].w);
    }
#pragma unroll
    for (int i = 0; i < 8; i++) {
        uint32_t* d = &Bs[(lrow + 16*i)*APAD + lwrd];
        d[0] = pack_h2(rb[i].x, rb[i].y);
        d[1] = pack_h2(rb[i].z, rb[i].w);
    }
    __syncthreads();

    const int T = K / HBK;
    int buf = 0;
    for (int t = 0; t < T; t++) {
        if (t + 1 < T) {
            const int k0 = (t + 1) * HBK;
#pragma unroll
            for (int i = 0; i < 8; i++)
                ra[i] = *(const float4*)&A[(size_t)(m0 + lrow + 16*i)*lda + k0 + lcol];
#pragma unroll
            for (int i = 0; i < 8; i++)
                rb[i] = *(const float4*)&W[(size_t)(n0 + lrow + 16*i)*K + k0 + lcol];
        }

        const uint32_t* Ab = As + buf*GBM*APAD;
        const uint32_t* Bb = Bs + buf*128*APAD;
#pragma unroll
        for (int ks = 0; ks < 4; ks++) {
            const int kb = ks * 8;
            uint32_t af[4][4];
#pragma unroll
            for (int mt = 0; mt < 4; mt++) {
                const int rbse = warpM*64 + mt*16;
                af[mt][0] = Ab[(rbse + lr    )*APAD + kb + lc    ];
                af[mt][1] = Ab[(rbse + lr + 8)*APAD + kb + lc    ];
                af[mt][2] = Ab[(rbse + lr    )*APAD + kb + lc + 4];
                af[mt][3] = Ab[(rbse + lr + 8)*APAD + kb + lc + 4];
            }
            uint32_t bf[4][2];
#pragma unroll
            for (int nt = 0; nt < 4; nt++) {
                const int nb = warpN*32 + nt*8;
                bf[nt][0] = Bb[(nb + lr)*APAD + kb + lc    ];
                bf[nt][1] = Bb[(nb + lr)*APAD + kb + lc + 4];
            }
#pragma unroll
            for (int mt = 0; mt < 4; mt++)
#pragma unroll
                for (int nt = 0; nt < 4; nt++)
                    mma_f16(acc[mt][nt], af[mt][0], af[mt][1], af[mt][2], af[mt][3],
                            bf[nt][0], bf[nt][1]);
        }

        if (t + 1 < T) {
            uint32_t* An = As + (buf^1)*GBM*APAD;
            uint32_t* Bn = Bs + (buf^1)*128*APAD;
#pragma unroll
            for (int i = 0; i < 8; i++) {
                uint32_t* d = &An[(lrow + 16*i)*APAD + lwrd];
                d[0] = pack_h2(ra[i].x, ra[i].y);
                d[1] = pack_h2(ra[i].z, ra[i].w);
            }
#pragma unroll
            for (int i = 0; i < 8; i++) {
                uint32_t* d = &Bn[(lrow + 16*i)*APAD + lwrd];
                d[0] = pack_h2(rb[i].x, rb[i].y);
                d[1] = pack_h2(rb[i].z, rb[i].w);
            }
        }
        __syncthreads();
        buf ^= 1;
    }

#pragma unroll
    for (int mt = 0; mt < 4; mt++) {
#pragma unroll
        for (int nt = 0; nt < 4; nt++) {
#pragma unroll
            for (int e = 0; e < 4; e++) {
                const int row = m0 + warpM*64 + mt*16 + lr + (e >= 2 ? 8 : 0);
                const int col = n0 + warpN*32 + nt*8 + lc*2 + (e & 1);
                float vv = acc[mt][nt][e];
                if (EPI >= 1) vv += bias[col];
                if (EPI == 2) vv = 0.5f * vv * (1.f + erff(vv * 0.70710678118654752f));
                C[(size_t)row*N + col] = vv;
            }
        }
    }
}

template<int EPI>
__global__ __launch_bounds__(256) void gemm_w_kernel(
    const float* __restrict__ A, int lda,
    const float* __restrict__ W,
    const float* __restrict__ bias,
    float* __restrict__ C,
    int N, int K)
{
    gemm_w_body<EPI>(A, lda, W, bias, C, N, K);
}

// z-batched q/k/v: blockIdx.z selects (x,Wq,bq,q), (mem,Wk,bk,k), (mem,Wv,bv,v)
__global__ __launch_bounds__(256) void gemm_wqkv_kernel(
    const float* __restrict__ x,  const float* __restrict__ mem,
    const float* __restrict__ Wq, const float* __restrict__ Wk, const float* __restrict__ Wv,
    const float* __restrict__ bq, const float* __restrict__ bk, const float* __restrict__ bv,
    float* __restrict__ q, float* __restrict__ k, float* __restrict__ v)
{
    const int z = blockIdx.z;
    const float* A    = (z == 0) ? x  : mem;
    const float* W    = (z == 0) ? Wq : (z == 1 ? Wk : Wv);
    const float* bias = (z == 0) ? bq : (z == 1 ? bk : bv);
    float*       C    = (z == 0) ? q  : (z == 1 ? k  : v);
    gemm_w_body<1>(A, DM, W, bias, C, DM, DM);
}

// ---------------- narrow fp16 GEMM (verified R12) — N=64 x-proj only --------
template<int EPI>
__global__ __launch_bounds__(256) void gemm_h_kernel(
    const float* __restrict__ A, int lda,
    const float* __restrict__ W,
    const float* __restrict__ bias,
    float* __restrict__ C,
    int N, int K)
{
    extern __shared__ uint32_t sm[];
    uint32_t* As = sm;
    uint32_t* Bs = sm + 2*GBM*APAD;

    const int tid  = threadIdx.x;
    const int wid  = tid >> 5;
    const int lane = tid & 31;
    const int warpM = wid & 3;
    const int warpN = wid >> 2;
    const int m0 = blockIdx.y * GBM;
    const int n0 = blockIdx.x * GBN;

    const int lr = lane >> 2;
    const int lc = lane & 3;

    const int lrow = tid >> 4;
    const int lcol = (tid & 15) * 4;
    const int lwrd = lcol >> 1;

    float acc[2][4][4];
#pragma unroll
    for (int i = 0; i < 2; i++)
#pragma unroll
        for (int j = 0; j < 4; j++)
#pragma unroll
            for (int e = 0; e < 4; e++) acc[i][j][e] = 0.f;

    float4 ra[8], rb[4];

#pragma unroll
    for (int i = 0; i < 8; i++)
        ra[i] = *(const float4*)&A[(size_t)(m0 + lrow + 16*i)*lda + lcol];
#pragma unroll
    for (int i = 0; i < 4; i++)
        rb[i] = *(const float4*)&W[(size_t)(n0 + lrow + 16*i)*K + lcol];
#pragma unroll
    for (int i = 0; i < 8; i++) {
        uint32_t* d = &As[(lrow + 16*i)*APAD + lwrd];
        d[0] = pack_h2(ra[i].x, ra[i].y);
        d[1] = pack_h2(ra[i].z, ra[i].w);
    }
#pragma unroll
    for (int i = 0; i < 4; i++) {
        uint32_t* d = &Bs[(lrow + 16*i)*APAD + lwrd];
        d[0] = pack_h2(rb[i].x, rb[i].y);
        d[1] = pack_h2(rb[i].z, rb[i].w);
    }
    __syncthreads();

    const int T = K / HBK;
    int buf = 0;
    for (int t = 0; t < T; t++) {
        if (t + 1 < T) {
            const int k0 = (t + 1) * HBK;
#pragma unroll
            for (int i = 0; i < 8; i++)
                ra[i] = *(const float4*)&A[(size_t)(m0 + lrow + 16*i)*lda + k0 + lcol];
#pragma unroll
            for (int i = 0; i < 4; i++)
                rb[i] = *(const float4*)&W[(size_t)(n0 + lrow + 16*i)*K + k0 + lcol];
        }

        const uint32_t* Ab = As + buf*GBM*APAD;
        const uint32_t* Bb = Bs + buf*GBN*APAD;
#pragma unroll
        for (int ks = 0; ks < 4; ks++) {
            const int kb = ks * 8;
            uint32_t af[2][4];
#pragma unroll
            for (int mt = 0; mt < 2; mt++) {
                const int rbse = warpM*32 + mt*16;
                af[mt][0] = Ab[(rbse + lr    )*APAD + kb + lc    ];
                af[mt][1] = Ab[(rbse + lr + 8)*APAD + kb + lc    ];
                af[mt][2] = Ab[(rbse + lr    )*APAD + kb + lc + 4];
                af[mt][3] = Ab[(rbse + lr + 8)*APAD + kb + lc + 4];
            }
            uint32_t bf[4][2];
#pragma unroll
            for (int nt = 0; nt < 4; nt++) {
                const int nb = warpN*32 + nt*8;
                bf[nt][0] = Bb[(nb + lr)*APAD + kb + lc    ];
                bf[nt][1] = Bb[(nb + lr)*APAD + kb + lc + 4];
            }
#pragma unroll
            for (int mt = 0; mt < 2; mt++)
#pragma unroll
                for (int nt = 0; nt < 4; nt++)
                    mma_f16(acc[mt][nt], af[mt][0], af[mt][1], af[mt][2], af[mt][3],
                            bf[nt][0], bf[nt][1]);
        }

        if (t + 1 < T) {
            uint32_t* An = As + (buf^1)*GBM*APAD;
            uint32_t* Bn = Bs + (buf^1)*GBN*APAD;
#pragma unroll
            for (int i = 0; i < 8; i++) {
                uint32_t* d = &An[(lrow + 16*i)*APAD + lwrd];
                d[0] = pack_h2(ra[i].x, ra[i].y);
                d[1] = pack_h2(ra[i].z, ra[i].w);
            }
#pragma unroll
            for (int i = 0; i < 4; i++) {
                uint32_t* d = &Bn[(lrow + 16*i)*APAD + lwrd];
                d[0] = pack_h2(rb[i].x, rb[i].y);
                d[1] = pack_h2(rb[i].z, rb[i].w);
            }
        }
        __syncthreads();
        buf ^= 1;
    }

#pragma unroll
    for (int mt = 0; mt < 2; mt++) {
#pragma unroll
        for (int nt = 0; nt < 4; nt++) {
#pragma unroll
            for (int e = 0; e < 4; e++) {
                const int row = m0 + warpM*32 + mt*16 + lr + (e >= 2 ? 8 : 0);
                const int col = n0 + warpN*32 + nt*8 + lc*2 + (e & 1);
                float vv = acc[mt][nt][e];
                if (EPI >= 1) vv += bias[col];
                if (EPI == 2) vv = 0.5f * vv * (1.f + erff(vv * 0.70710678118654752f));
                C[(size_t)row*N + col] = vv;
            }
        }
    }
}

// ---------------- tf32 GEMM (kept for K=32 dt-projection, EPI=3 softplus) ---
#define GBK 32
template<int EPI>
__global__ __launch_bounds__(256) void gemm_tc_kernel(
    const float* __restrict__ A, int lda,
    const float* __restrict__ W,
    const float* __restrict__ bias,
    float* __restrict__ C,
    int N, int K)
{
    extern __shared__ uint32_t sm[];
    uint32_t* As = sm;
    uint32_t* Bs = sm + 2*GBM*APAD;

    const int tid  = threadIdx.x;
    const int wid  = tid >> 5;
    const int lane = tid & 31;
    const int warpM = wid & 3;
    const int warpN = wid >> 2;
    const int m0 = blockIdx.y * GBM;
    const int n0 = blockIdx.x * GBN;
    const int lr = lane >> 2;
    const int lc = lane & 3;
    const int lrow = tid >> 3;
    const int lcol = (tid & 7) * 4;

    float acc[2][4][4];
#pragma unroll
    for (int i = 0; i < 2; i++)
#pragma unroll
        for (int j = 0; j < 4; j++)
#pragma unroll
            for (int e = 0; e < 4; e++) acc[i][j][e] = 0.f;

    float4 ra[4], rb[2];
    {
#pragma unroll
        for (int i = 0; i < 4; i++)
            ra[i] = *(const float4*)&A[(size_t)(m0 + lrow + 32*i)*lda + lcol];
#pragma unroll
        for (int i = 0; i < 2; i++)
            rb[i] = *(const float4*)&W[(size_t)(n0 + lrow + 32*i)*K + lcol];
#pragma unroll
        for (int i = 0; i < 4; i++) {
            uint32_t* d = &As[(lrow + 32*i)*APAD + lcol];
            d[0] = f2tf32(ra[i].x); d[1] = f2tf32(ra[i].y);
            d[2] = f2tf32(ra[i].z); d[3] = f2tf32(ra[i].w);
        }
#pragma unroll
        for (int i = 0; i < 2; i++) {
            uint32_t* d = &Bs[(lrow + 32*i)*APAD + lcol];
            d[0] = f2tf32(rb[i].x); d[1] = f2tf32(rb[i].y);
            d[2] = f2tf32(rb[i].z); d[3] = f2tf32(rb[i].w);
        }
    }
    __syncthreads();

    const int T = K / GBK;
    int buf = 0;
    for (int t = 0; t < T; t++) {
        if (t + 1 < T) {
            const int k0 = (t + 1) * GBK;
#pragma unroll
            for (int i = 0; i < 4; i++)
                ra[i] = *(const float4*)&A[(size_t)(m0 + lrow + 32*i)*lda + k0 + lcol];
#pragma unroll
            for (int i = 0; i < 2; i++)
                rb[i] = *(const float4*)&W[(size_t)(n0 + lrow + 32*i)*K + k0 + lcol];
        }
        const uint32_t* Ab = As + buf*GBM*APAD;
        const uint32_t* Bb = Bs + buf*GBN*APAD;
#pragma unroll
        for (int ks = 0; ks < 4; ks++) {
            const int kb = ks * 8;
            uint32_t af[2][4];
#pragma unroll
            for (int mt = 0; mt < 2; mt++) {
                const int rbse = warpM*32 + mt*16;
                af[mt][0] = Ab[(rbse + lr    )*APAD + kb + lc    ];
                af[mt][1] = Ab[(rbse + lr + 8)*APAD + kb + lc    ];
                af[mt][2] = Ab[(rbse + lr    )*APAD + kb + lc + 4];
                af[mt][3] = Ab[(rbse + lr + 8)*APAD + kb + lc + 4];
            }
            uint32_t bf[4][2];
#pragma unroll
            for (int nt = 0; nt < 4; nt++) {
                const int nb = warpN*32 + nt*8;
                bf[nt][0] = Bb[(nb + lr)*APAD + kb + lc    ];
                bf[nt][1] = Bb[(nb + lr)*APAD + kb + lc + 4];
            }
#pragma unroll
            for (int mt = 0; mt < 2; mt++)
#pragma unroll
                for (int nt = 0; nt < 4; nt++)
                    mma_tf32(acc[mt][nt], af[mt][0], af[mt][1], af[mt][2], af[mt][3],
                             bf[nt][0], bf[nt][1]);
        }
        if (t + 1 < T) {
            uint32_t* An = As + (buf^1)*GBM*APAD;
            uint32_t* Bn = Bs + (buf^1)*GBN*APAD;
#pragma unroll
            for (int i = 0; i < 4; i++) {
                uint32_t* d = &An[(lrow + 32*i)*APAD + lcol];
                d[0] = f2tf32(ra[i].x); d[1] = f2tf32(ra[i].y);
                d[2] = f2tf32(ra[i].z); d[3] = f2tf32(ra[i].w);
            }
#pragma unroll
            for (int i = 0; i < 2; i++) {
                uint32_t* d = &Bn[(lrow + 32*i)*APAD + lcol];
                d[0] = f2tf32(rb[i].x); d[1] = f2tf32(rb[i].y);
                d[2] = f2tf32(rb[i].z); d[3] = f2tf32(rb[i].w);
            }
        }
        __syncthreads();
        buf ^= 1;
    }

#pragma unroll
    for (int mt = 0; mt < 2; mt++) {
#pragma unroll
        for (int nt = 0; nt < 4; nt++) {
#pragma unroll
            for (int e = 0; e < 4; e++) {
                const int row = m0 + warpM*32 + mt*16 + lr + (e >= 2 ? 8 : 0);
                const int col = n0 + warpN*32 + nt*8 + lc*2 + (e & 1);
                float vv = acc[mt][nt][e];
                if (EPI >= 1) vv += bias[col];
                if (EPI == 3) vv = (vv > 20.f) ? vv : log1pf(expf(vv));
                C[(size_t)row*N + col] = vv;
            }
        }
    }
}

// ---------------- fp16 flash attention: 128 q-rows / 8 warps per block ------
#define KWST 36
#define VTST 17
#define PST  20

__global__ __launch_bounds__(256) void attn_h_kernel(
    const float* __restrict__ q, const float* __restrict__ k,
    const float* __restrict__ v, float* __restrict__ out)
{
    __shared__ uint32_t Ks[32*KWST];          // [key][ch-word 0..31]
    __shared__ uint32_t Vt[64*VTST];          // [ch][key-word 0..15]
    __shared__ uint32_t Ps[8][16*PST];        // per-warp [row][key-word]

    const int b = blockIdx.z, h = blockIdx.y;
    const int q0 = blockIdx.x * 128;
    const int tid = threadIdx.x;
    const int wid = tid >> 5;      // 0..7
    const int lane = tid & 31;
    const int lr = lane >> 2;
    const int lc = lane & 3;

    uint32_t Qf[4][4];
    {
        const float* q_r0 = q + (size_t)(b*SEQ + q0 + wid*16 + lr    )*DM + h*DH;
        const float* q_r1 = q + (size_t)(b*SEQ + q0 + wid*16 + lr + 8)*DM + h*DH;
#pragma unroll
        for (int ks = 0; ks < 4; ks++) {
            const int c0 = ks*16 + 2*lc;
            Qf[ks][0] = pack_h2(q_r0[c0    ]*0.125f, q_r0[c0 + 1]*0.125f);
            Qf[ks][1] = pack_h2(q_r1[c0    ]*0.125f, q_r1[c0 + 1]*0.125f);
            Qf[ks][2] = pack_h2(q_r0[c0 + 8]*0.125f, q_r0[c0 + 9]*0.125f);
            Qf[ks][3] = pack_h2(q_r1[c0 + 8]*0.125f, q_r1[c0 + 9]*0.125f);
        }
    }

    float Oacc[8][4];
#pragma unroll
    for (int nb = 0; nb < 8; nb++)
#pragma unroll
        for (int e = 0; e < 4; e++) Oacc[nb][e] = 0.f;
    float m0 = -1e30f, m1 = -1e30f, l0 = 0.f, l1 = 0.f;

    for (int t0 = 0; t0 < SEQ; t0 += 32) {
        __syncthreads();
        // K tile: 256 threads, 8 threads/key, 8 ch each -> 4 half2 words
        {
            const int j = tid >> 3;              // key 0..31
            const int c0 = (tid & 7) * 8;        // channel base
            const float4 k0v = *(const float4*)&k[(size_t)(b*SEQ + t0 + j)*DM + h*DH + c0];
            const float4 k1v = *(const float4*)&k[(size_t)(b*SEQ + t0 + j)*DM + h*DH + c0 + 4];
            uint32_t* dst = &Ks[j*KWST + (c0 >> 1)];
            dst[0] = pack_h2(k0v.x, k0v.y);
            dst[1] = pack_h2(k0v.z, k0v.w);
            dst[2] = pack_h2(k1v.x, k1v.y);
            dst[3] = pack_h2(k1v.z, k1v.w);
        }
        // V tile transposed: thread owns key-pair jp, 4 channels
        {
            const int jp = tid >> 4;             // key-pair 0..15
            const int c4 = (tid & 15) * 4;       // channel base
            const float4 a0 = *(const float4*)&v[(size_t)(b*SEQ + t0 + 2*jp    )*DM + h*DH + c4];
            const float4 b0 = *(const float4*)&v[(size_t)(b*SEQ + t0 + 2*jp + 1)*DM + h*DH + c4];
            Vt[(c4+0)*VTST + jp] = pack_h2(a0.x, b0.x);
            Vt[(c4+1)*VTST + jp] = pack_h2(a0.y, b0.y);
            Vt[(c4+2)*VTST + jp] = pack_h2(a0.z, b0.z);
            Vt[(c4+3)*VTST + jp] = pack_h2(a0.w, b0.w);
        }
        __syncthreads();

        // S = Q @ K^T
        float Sacc[4][4];
#pragma unroll
        for (int nb = 0; nb < 4; nb++)
#pragma unroll
            for (int e = 0; e < 4; e++) Sacc[nb][e] = 0.f;
#pragma unroll
        for (int ks = 0; ks < 4; ks++) {
            const int kb = ks * 8;
            uint32_t bf[4][2];
#pragma unroll
            for (int nb = 0; nb < 4; nb++) {
                bf[nb][0] = Ks[(nb*8 + lr)*KWST + kb + lc    ];
                bf[nb][1] = Ks[(nb*8 + lr)*KWST + kb + lc + 4];
            }
#pragma unroll
            for (int nb = 0; nb < 4; nb++)
                mma_f16(Sacc[nb], Qf[ks][0], Qf[ks][1], Qf[ks][2], Qf[ks][3],
                        bf[nb][0], bf[nb][1]);
        }

        // online softmax
        float tmax0 = -1e30f, tmax1 = -1e30f;
#pragma unroll
        for (int nb = 0; nb < 4; nb++) {
            tmax0 = fmaxf(tmax0, fmaxf(Sacc[nb][0], Sacc[nb][1]));
            tmax1 = fmaxf(tmax1, fmaxf(Sacc[nb][2], Sacc[nb][3]));
        }
        tmax0 = fmaxf(tmax0, __shfl_xor_sync(0xffffffffu, tmax0, 1));
        tmax0 = fmaxf(tmax0, __shfl_xor_sync(0xffffffffu, tmax0, 2));
        tmax1 = fmaxf(tmax1, __shfl_xor_sync(0xffffffffu, tmax1, 1));
        tmax1 = fmaxf(tmax1, __shfl_xor_sync(0xffffffffu, tmax1, 2));

        const float m0n = fmaxf(m0, tmax0), m1n = fmaxf(m1, tmax1);
        const float c0 = __expf(m0 - m0n), c1 = __expf(m1 - m1n);
        m0 = m0n; m1 = m1n;

        float s0 = 0.f, s1 = 0.f;
        uint32_t* Pw = Ps[wid];
#pragma unroll
        for (int nb = 0; nb < 4; nb++) {
            const float p00 = __expf(Sacc[nb][0] - m0);
            const float p01 = __expf(Sacc[nb][1] - m0);
            const float p10 = __expf(Sacc[nb][2] - m1);
            const float p11 = __expf(Sacc[nb][3] - m1);
            s0 += p00 + p01; s1 += p10 + p11;
            Pw[(lr    )*PST + nb*4 + lc] = pack_h2(p00, p01);
            Pw[(lr + 8)*PST + nb*4 + lc] = pack_h2(p10, p11);
        }
        s0 += __shfl_xor_sync(0xffffffffu, s0, 1);
        s0 += __shfl_xor_sync(0xffffffffu, s0, 2);
        s1 += __shfl_xor_sync(0xffffffffu, s1, 1);
        s1 += __shfl_xor_sync(0xffffffffu, s1, 2);
        l0 = l0*c0 + s0;
        l1 = l1*c1 + s1;

#pragma unroll
        for (int nb = 0; nb < 8; nb++) {
            Oacc[nb][0] *= c0; Oacc[nb][1] *= c0;
            Oacc[nb][2] *= c1; Oacc[nb][3] *= c1;
        }
        __syncwarp();

        // O += P @ V
#pragma unroll
        for (int ks = 0; ks < 2; ks++) {
            const int kb = ks * 8;
            uint32_t Pf[4];
            Pf[0] = Pw[(lr    )*PST + kb + lc    ];
            Pf[1] = Pw[(lr + 8)*PST + kb + lc    ];
            Pf[2] = Pw[(lr    )*PST + kb + lc + 4];
            Pf[3] = Pw[(lr + 8)*PST + kb + lc + 4];
#pragma unroll
            for (int nb = 0; nb < 8; nb++) {
                uint32_t vf0 = Vt[(nb*8 + lr)*VTST + kb + lc    ];
                uint32_t vf1 = Vt[(nb*8 + lr)*VTST + kb + lc + 4];
                mma_f16(Oacc[nb], Pf[0], Pf[1], Pf[2], Pf[3], vf0, vf1);
            }
        }
    }

    const float inv0 = 1.f / l0, inv1 = 1.f / l1;
    float* o_r0 = out + (size_t)(b*SEQ + q0 + wid*16 + lr    )*DM + h*DH;
    float* o_r1 = out + (size_t)(b*SEQ + q0 + wid*16 + lr + 8)*DM + h*DH;
#pragma unroll
    for (int nb = 0; nb < 8; nb++) {
        o_r0[nb*8 + lc*2    ] = Oacc[nb][0] * inv0;
        o_r0[nb*8 + lc*2 + 1] = Oacc[nb][1] * inv0;
        o_r1[nb*8 + lc*2    ] = Oacc[nb][2] * inv1;
        o_r1[nb*8 + lc*2 + 1] = Oacc[nb][3] * inv1;
    }
}

// ---------------- layernorm(a + r): one warp per row ------------------------
__global__ __launch_bounds__(128) void ln_kernel(
    const float* __restrict__ a, const float* __restrict__ r,
    const float* __restrict__ g, const float* __restrict__ bt,
    float* __restrict__ out)
{
    const int row  = blockIdx.x*4 + (threadIdx.x >> 5);
    const int lane = threadIdx.x & 31;
    const size_t base = (size_t)row * DM;

    float vv[16];
    float sum = 0.f;
#pragma unroll
    for (int i = 0; i < 16; i++) {
        const int e = lane + i*32;
        vv[i] = a[base+e] + r[base+e];
        sum += vv[i];
    }
#pragma unroll
    for (int o = 16; o > 0; o >>= 1) sum += __shfl_xor_sync(0xffffffffu, sum, o);
    const float mu = sum * (1.f/DM);

    float sq = 0.f;
#pragma unroll
    for (int i = 0; i < 16; i++) { const float d = vv[i] - mu; sq = fmaf(d, d, sq); }
#pragma unroll
    for (int o = 16; o > 0; o >>= 1) sq += __shfl_xor_sync(0xffffffffu, sq, o);
    const float rstd = rsqrtf(sq * (1.f/DM) + 1e-5f);

#pragma unroll
    for (int i = 0; i < 16; i++) {
        const int e = lane + i*32;
        out[base+e] = (vv[i]-mu)*rstd*g[e] + bt[e];
    }
}

// ---------------- depthwise causal conv (D_CONV=4) + SiLU -------------------
__global__ void conv_silu_kernel(
    const float* __restrict__ xz, const float* __restrict__ cw,
    const float* __restrict__ cb, float* __restrict__ u)
{
    const int idx = blockIdx.x*256 + threadIdx.x;
    const int d = idx & (DI-1);
    const int t = (idx >> 10) & (SEQ-1);
    const int b = idx >> 20;
    float s = cb[d];
#pragma unroll
    for (int j = 0; j < 4; j++) {
        const int tt = t - 3 + j;
        if (tt >= 0)
            s = fmaf(xz[((size_t)(b*SEQ + tt) << 11) + d], cw[d*4 + j], s);
    }
    const float sg = 1.f / (1.f + __expf(-s));
    u[idx] = s * sg;
}

// ---------------- selective scan: thread-pair per channel (s split 8+8) -----
__global__ __launch_bounds__(64) void scan_kernel(
    const float* __restrict__ dt, const float* __restrict__ u,
    const float* __restrict__ xz, const float* __restrict__ xdbl,
    const float* __restrict__ A_log, const float* __restrict__ D_p,
    float* __restrict__ yout)
{
    const int b = blockIdx.x >> 5;
    const int dbase = (blockIdx.x & 31) << 5;
    const int ch = threadIdx.x >> 1;          // 0..31
    const int sh = (threadIdx.x & 1) * 8;     // state offset 0 or 8
    const int d = dbase + ch;

    float A[8];
#pragma unroll
    for (int s = 0; s < 8; s++) A[s] = -expf(A_log[d*DS + sh + s]);
    float h[8];
#pragma unroll
    for (int s = 0; s < 8; s++) h[s] = 0.f;
    const float Dp = D_p[d];

    __shared__ float Bs[64][DS];
    __shared__ float Cs[64][DS];
    __shared__ float dts[64][32];
    __shared__ float us [64][32];
    __shared__ float zs [64][32];

    for (int t0 = 0; t0 < SEQ; t0 += 64) {
        __syncthreads();
        for (int i = threadIdx.x; i < 64*DS; i += 64) {
            const int tt = i >> 4, s = i & 15;
            const size_t rb = (size_t)(b*SEQ + t0 + tt) * 64;
            Bs[tt][s] = xdbl[rb + DTR + s];
            Cs[tt][s] = xdbl[rb + DTR + DS + s];
        }
        for (int i = threadIdx.x; i < 64*8; i += 64) {
            const int tt = i >> 3, c4 = (i & 7) * 4;
            const size_t ro = (size_t)(b*SEQ + t0 + tt);
            *(float4*)&dts[tt][c4] = *(const float4*)&dt[ro*DI + dbase + c4];
            *(float4*)&us [tt][c4] = *(const float4*)&u [ro*DI + dbase + c4];
            *(float4*)&zs [tt][c4] = *(const float4*)&xz[(ro << 11) + DI + dbase + c4];
        }
        __syncthreads();

        for (int tt = 0; tt < 64; tt++) {
            const float dtv = dts[tt][ch];
            const float uv  = us [tt][ch];
            const float du  = dtv * uv;
            float y = 0.f;
#pragma unroll
            for (int s = 0; s < 8; s++) {
                const float dA = __expf(dtv * A[s]);
                h[s] = fmaf(h[s], dA, du * Bs[tt][sh + s]);
                y = fmaf(h[s], Cs[tt][sh + s], y);
            }
            y += __shfl_xor_sync(0xffffffffu, y, 1);
            if ((threadIdx.x & 1) == 0) {
                const float zv = zs[tt][ch];
                const float sg = zv / (1.f + __expf(-zv));
                yout[(size_t)(b*SEQ + t0 + tt)*DI + d] = (y + uv*Dp) * sg;
            }
        }
    }
}

// ---------------- launcher --------------------------------------------------
extern "C" void kernel_launch(void* const* d_in, const int* /*in_sizes*/, int /*n_in*/,
                              void* d_out, int /*out_size*/)
{
    const float* x      = (const float*)d_in[0];
    const float* mem    = (const float*)d_in[1];
    const float* Wq     = (const float*)d_in[2];
    const float* bq     = (const float*)d_in[3];
    const float* Wk     = (const float*)d_in[4];
    const float* bk     = (const float*)d_in[5];
    const float* Wv     = (const float*)d_in[6];
    const float* bv     = (const float*)d_in[7];
    const float* Wo     = (const float*)d_in[8];
    const float* bo     = (const float*)d_in[9];
    const float* ln1g   = (const float*)d_in[10];
    const float* ln1b   = (const float*)d_in[11];
    const float* ln2g   = (const float*)d_in[12];
    const float* ln2b   = (const float*)d_in[13];
    const float* ln3g   = (const float*)d_in[14];
    const float* ln3b   = (const float*)d_in[15];
    const float* W_in   = (const float*)d_in[16];
    const float* conv_w = (const float*)d_in[17];
    const float* conv_b = (const float*)d_in[18];
    const float* W_xprj = (const float*)d_in[19];
    const float* W_dt   = (const float*)d_in[20];
    const float* b_dt   = (const float*)d_in[21];
    const float* A_log  = (const float*)d_in[22];
    const float* D_p    = (const float*)d_in[23];
    const float* W_out  = (const float*)d_in[24];
    const float* W1     = (const float*)d_in[25];
    const float* b1     = (const float*)d_in[26];
    const float* W2     = (const float*)d_in[27];
    const float* b2     = (const float*)d_in[28];

    float *q, *k, *v, *attn, *tmp, *x1, *x2, *xz, *u, *xdbl, *dtb, *y, *ffn;
    cudaGetSymbolAddress((void**)&q,    g_q);
    cudaGetSymbolAddress((void**)&k,    g_k);
    cudaGetSymbolAddress((void**)&v,    g_v);
    cudaGetSymbolAddress((void**)&attn, g_attn);
    cudaGetSymbolAddress((void**)&tmp,  g_tmp);
    cudaGetSymbolAddress((void**)&x1,   g_x1);
    cudaGetSymbolAddress((void**)&x2,   g_x2);
    cudaGetSymbolAddress((void**)&xz,   g_xz);
    cudaGetSymbolAddress((void**)&u,    g_u);
    cudaGetSymbolAddress((void**)&xdbl, g_xdbl);
    cudaGetSymbolAddress((void**)&dtb,  g_dt);
    cudaGetSymbolAddress((void**)&y,    g_y);
    cudaGetSymbolAddress((void**)&ffn,  g_ffn);

    // opt in to >48KB dynamic smem (idempotent, host-side, capture-safe)
    cudaFuncSetAttribute(gemm_w_kernel<0>, cudaFuncAttributeMaxDynamicSharedMemorySize, SMEM_W);
    cudaFuncSetAttribute(gemm_w_kernel<1>, cudaFuncAttributeMaxDynamicSharedMemorySize, SMEM_W);
    cudaFuncSetAttribute(gemm_w_kernel<2>, cudaFuncAttributeMaxDynamicSharedMemorySize, SMEM_W);
    cudaFuncSetAttribute(gemm_wqkv_kernel, cudaFuncAttributeMaxDynamicSharedMemorySize, SMEM_W);
    cudaFuncSetAttribute(gemm_h_kernel<0>, cudaFuncAttributeMaxDynamicSharedMemorySize, SMEM_GEMM);
    cudaFuncSetAttribute(gemm_tc_kernel<3>, cudaFuncAttributeMaxDynamicSharedMemorySize, SMEM_GEMM);

    const dim3 gRowW(DM/128,   MTOK/128);      // (4, 32)  wide N=512
    const dim3 gQKV(DM/128,    MTOK/128, 3);   // (4, 32, 3)
    const dim3 gBigW(2048/128, MTOK/128);      // (16, 32) wide N=2048
    const dim3 gXp (64/GBN,    MTOK/GBM);      // (1, 32)
    const dim3 gDt (DI/GBN,    MTOK/GBM);      // (16, 32)

    // --- cross attention ---
    gemm_wqkv_kernel<<<gQKV, 256, SMEM_W>>>(x, mem, Wq, Wk, Wv, bq, bk, bv, q, k, v);
    attn_h_kernel<<<dim3(SEQ/128, NH, BATCH), 256>>>(q, k, v, attn);
    gemm_w_kernel<1><<<gRowW, 256, SMEM_W>>>(attn, DM, Wo, bo, tmp, DM, DM);
    ln_kernel<<<MTOK/4, 128>>>(x, tmp, ln1g, ln1b, x1);

    // --- mamba ---
    gemm_w_kernel<0><<<gBigW, 256, SMEM_W>>>(x1, DM, W_in, nullptr, xz, 2*DI, DM);
    conv_silu_kernel<<<(MTOK*DI)/256, 256>>>(xz, conv_w, conv_b, u);
    gemm_h_kernel<0><<<gXp, 256, SMEM_GEMM>>>(u, DI, W_xprj, nullptr, xdbl, 64, DI);
    gemm_tc_kernel<3><<<gDt, 256, SMEM_GEMM>>>(xdbl, 64, W_dt, b_dt, dtb, DI, DTR);
    scan_kernel<<<128, 64>>>(dtb, u, xz, xdbl, A_log, D_p, y);
    gemm_w_kernel<0><<<gRowW, 256, SMEM_W>>>(y, DI, W_out, nullptr, tmp, DM, DI);
    ln_kernel<<<MTOK/4, 128>>>(x1, tmp, ln2g, ln2b, x2);

    // --- ffn ---
    gemm_w_kernel<2><<<gBigW, 256, SMEM_W>>>(x2, DM, W1, b1, ffn, 2048, DM);
    gemm_w_kernel<1><<<gRowW, 256, SMEM_W>>>(ffn, 2048, W2, b2, tmp, DM, 2048);
    ln_kernel<<<MTOK/4, 128>>>(x2, tmp, ln3g, ln3b, (float*)d_out);
}